// round 6
// baseline (speedup 1.0000x reference)
#include <cuda_runtime.h>
#include <cuda_bf16.h>

// Integrate-and-fire spiking neuron, 3 phases, per-pixel independent.
// T1 = T2 = 8, L = 8, EPS = -8e-5, thre = thresh[0]/8.
//
// x layout:   x[t*S + p]   for t in [0,8), p in [0, S) with S = B*C*H*W
// out layout: out[t*S + p]
//
// Pure streaming kernel: 128 MiB in + 128 MiB out, no reuse.

#define IF_T1 8
#define IF_T2 8
#define IF_RELAX 7            // T3 - 1 = max(T1,T2) - 1
#define IF_EPS (-8e-05f)

__global__ __launch_bounds__(256)
void IF_88957362634870_kernel(const float4* __restrict__ x,
                              const float* __restrict__ thresh,
                              float4* __restrict__ out,
                              int S4) {
    int i = blockIdx.x * blockDim.x + threadIdx.x;
    if (i >= S4) return;

    // thresh/L with L=8: *0.125f is exact (power of two), matches JAX fp32.
    const float thre = thresh[0] * 0.125f;

    // Issue all 8 time-step loads up front: 8 independent 16B LDGs per
    // thread -> MLP=8, DRAM latency fully overlapped.
    float4 xs[IF_T1];
#pragma unroll
    for (int t = 0; t < IF_T1; t++) {
        xs[t] = x[i + t * S4];
    }

    float mem[4], sc[4];
#pragma unroll
    for (int c = 0; c < 4; c++) {
        mem[c] = 0.5f * thre;
        sc[c]  = 0.0f;
    }

    // ---- Phase 1: integrate-and-fire over T1 frames ----
#pragma unroll
    for (int t = 0; t < IF_T1; t++) {
        float xv[4] = {xs[t].x, xs[t].y, xs[t].z, xs[t].w};
#pragma unroll
        for (int c = 0; c < 4; c++) {
            mem[c] = mem[c] + xv[c];
            float spike = ((mem[c] - thre) >= IF_EPS) ? thre : 0.0f;
            mem[c] = mem[c] - spike;
            sc[c]  = sc[c] + spike;
        }
    }

    // ---- Phase 2: T3-1 relaxation steps with reverse spikes ----
#pragma unroll
    for (int s = 0; s < IF_RELAX; s++) {
#pragma unroll
        for (int c = 0; c < 4; c++) {
            float spike = ((mem[c] - thre) >= IF_EPS) ? thre : 0.0f;
            float rev   = ((-mem[c]) > 0.0f) ? thre : 0.0f;
            mem[c] = (mem[c] - spike) + rev;   // same assoc order as JAX
            sc[c]  = (sc[c] + spike) - rev;
        }
    }

    // ---- Phase 3: re-emit spike count as T2 output spikes ----
    // mem := sc, then emit one spike level per step; store immediately so
    // output registers don't all stay live.
#pragma unroll
    for (int c = 0; c < 4; c++) mem[c] = sc[c];

#pragma unroll
    for (int t = 0; t < IF_T2; t++) {
        float sp[4];
#pragma unroll
        for (int c = 0; c < 4; c++) {
            sp[c]  = ((mem[c] - thre) >= IF_EPS) ? thre : 0.0f;
            mem[c] = mem[c] - sp[c];
        }
        float4 o;
        o.x = sp[0]; o.y = sp[1]; o.z = sp[2]; o.w = sp[3];
        out[i + t * S4] = o;
    }
}

extern "C" void kernel_launch(void* const* d_in, const int* in_sizes, int n_in,
                              void* d_out, int out_size) {
    const float4* x      = (const float4*)d_in[0];
    const float*  thresh = (const float*)d_in[1];
    float4*       out    = (float4*)d_out;

    // Elements per frame: total / T1; float4s per frame: /4.
    int S  = in_sizes[0] / IF_T1;
    int S4 = S / 4;

    int threads = 256;
    int blocks  = (S4 + threads - 1) / threads;
    IF_88957362634870_kernel<<<blocks, threads>>>(x, thresh, out, S4);
}

// round 7
// speedup vs baseline: 1.0156x; 1.0156x over previous
#include <cuda_runtime.h>
#include <cuda_bf16.h>

// Integrate-and-fire spiking neuron, 3 phases, per-pixel independent.
// T1 = T2 = 8, L = 8, EPS = -8e-5, thre = thresh[0]/8.
//
// x layout:   x[t*S + p]   for t in [0,8), p in [0, S) with S = B*C*H*W
// out layout: out[t*S + p]
//
// Pure streaming kernel: 128 MiB in + 128 MiB out, no reuse.
// R6 changes vs R2 baseline:
//  - __ldcs / __stcs (evict-first): input is read-once, output write-once;
//    keeps dirty output lines from lingering in L2 and fighting the next
//    graph-replay's read stream.
//  - __launch_bounds__(256, 6): lift the 32-reg cap so ptxas can front-batch
//    all 8 LDG.128s (MLP=8) instead of interleaving loads with phase 1.

#define IF_T1 8
#define IF_T2 8
#define IF_RELAX 7            // T3 - 1 = max(T1,T2) - 1
#define IF_EPS (-8e-05f)

__global__ __launch_bounds__(256, 6)
void IF_88957362634870_kernel(const float4* __restrict__ x,
                              const float* __restrict__ thresh,
                              float4* __restrict__ out,
                              int S4) {
    int i = blockIdx.x * blockDim.x + threadIdx.x;
    if (i >= S4) return;

    // thresh/L with L=8: *0.125f is exact (power of two), matches JAX fp32.
    const float thre = __ldg(thresh) * 0.125f;

    // Issue all 8 time-step loads up front: 8 independent 16B LDGs per
    // thread -> MLP=8, DRAM latency fully overlapped. Evict-first: data is
    // read exactly once.
    float4 xs[IF_T1];
#pragma unroll
    for (int t = 0; t < IF_T1; t++) {
        xs[t] = __ldcs(&x[i + t * S4]);
    }

    float mem[4], sc[4];
#pragma unroll
    for (int c = 0; c < 4; c++) {
        mem[c] = 0.5f * thre;
        sc[c]  = 0.0f;
    }

    // ---- Phase 1: integrate-and-fire over T1 frames ----
#pragma unroll
    for (int t = 0; t < IF_T1; t++) {
        float xv[4] = {xs[t].x, xs[t].y, xs[t].z, xs[t].w};
#pragma unroll
        for (int c = 0; c < 4; c++) {
            mem[c] = mem[c] + xv[c];
            float spike = ((mem[c] - thre) >= IF_EPS) ? thre : 0.0f;
            mem[c] = mem[c] - spike;
            sc[c]  = sc[c] + spike;
        }
    }

    // ---- Phase 2: T3-1 relaxation steps with reverse spikes ----
#pragma unroll
    for (int s = 0; s < IF_RELAX; s++) {
#pragma unroll
        for (int c = 0; c < 4; c++) {
            float spike = ((mem[c] - thre) >= IF_EPS) ? thre : 0.0f;
            float rev   = ((-mem[c]) > 0.0f) ? thre : 0.0f;
            mem[c] = (mem[c] - spike) + rev;   // same assoc order as JAX
            sc[c]  = (sc[c] + spike) - rev;
        }
    }

    // ---- Phase 3: re-emit spike count as T2 output spikes ----
    // mem := sc, then emit one spike level per step; store immediately
    // (streaming / evict-first: output is never re-read by this kernel).
#pragma unroll
    for (int c = 0; c < 4; c++) mem[c] = sc[c];

#pragma unroll
    for (int t = 0; t < IF_T2; t++) {
        float sp[4];
#pragma unroll
        for (int c = 0; c < 4; c++) {
            sp[c]  = ((mem[c] - thre) >= IF_EPS) ? thre : 0.0f;
            mem[c] = mem[c] - sp[c];
        }
        float4 o;
        o.x = sp[0]; o.y = sp[1]; o.z = sp[2]; o.w = sp[3];
        __stcs(&out[i + t * S4], o);
    }
}

extern "C" void kernel_launch(void* const* d_in, const int* in_sizes, int n_in,
                              void* d_out, int out_size) {
    const float4* x      = (const float4*)d_in[0];
    const float*  thresh = (const float*)d_in[1];
    float4*       out    = (float4*)d_out;

    // Elements per frame: total / T1; float4s per frame: /4.
    int S  = in_sizes[0] / IF_T1;
    int S4 = S / 4;

    int threads = 256;
    int blocks  = (S4 + threads - 1) / threads;
    IF_88957362634870_kernel<<<blocks, threads>>>(x, thresh, out, S4);
}